// round 3
// baseline (speedup 1.0000x reference)
#include <cuda_runtime.h>
#include <cstdint>

// Problem dims (fixed)
#define Bq 2
#define Vq 8
#define F_INq 64
#define F_OUTq 64
#define Rq 16
#define RVq 4
#define BV (Bq*Vq)                 // 16
#define ROWS_PER_BV 65536          // T*N*D
#define RPB 128                    // rows per block
#define TPB 128
#define XSTR 68                    // x row stride (floats): 17*row chunk banking, 16B aligned
#define YSTR 20                    // y row stride (floats): 5*row chunk banking, 16B aligned

__device__ float g_H[BV * Rq * F_OUTq];     // per-bv H = Ceff @ fac_out, [r][e]
__device__ float g_finT[F_INq * Rq];        // fac_in^T, [a][r]

// ---- packed f32x2 helpers -------------------------------------------------
__device__ __forceinline__ unsigned long long ffma2(unsigned long long a,
                                                    unsigned long long b,
                                                    unsigned long long c) {
    unsigned long long d;
    asm("fma.rn.f32x2 %0, %1, %2, %3;" : "=l"(d) : "l"(a), "l"(b), "l"(c));
    return d;
}
__device__ __forceinline__ unsigned long long pack2(float v) {
    unsigned long long d;
    asm("mov.b64 %0, {%1, %1};" : "=l"(d) : "f"(v));
    return d;
}

// ---- tiny precompute ------------------------------------------------------
__global__ void precompute_kernel(const int* __restrict__ var_idx,
                                  const float* __restrict__ core,        // (RV, R, R)
                                  const float* __restrict__ factor_vars, // (NVAR, RV)
                                  const float* __restrict__ fac_in,      // (R, F_IN)
                                  const float* __restrict__ fac_out) {   // (R, F_OUT)
    int bv = blockIdx.x;
    int e  = threadIdx.x;      // 0..63
    __shared__ float fvs[RVq];
    __shared__ float ceff[Rq * Rq];

    if (e < RVq) fvs[e] = factor_vars[var_idx[bv] * RVq + e];
    __syncthreads();

    for (int i = e; i < Rq * Rq; i += 64) {
        float s = 0.f;
        #pragma unroll
        for (int A = 0; A < RVq; ++A) s += fvs[A] * core[A * Rq * Rq + i];
        ceff[i] = s;
    }
    __syncthreads();

    #pragma unroll
    for (int r = 0; r < Rq; ++r) {
        float s = 0.f;
        #pragma unroll
        for (int c = 0; c < Rq; ++c) s += ceff[r * Rq + c] * fac_out[c * F_OUTq + e];
        g_H[bv * Rq * F_OUTq + r * F_OUTq + e] = s;
    }
    if (bv == 0) {
        #pragma unroll
        for (int r = 0; r < Rq; ++r) g_finT[e * Rq + r] = fac_in[r * F_INq + e];
    }
}

// ---- main fused kernel -----------------------------------------------------
__global__ void __launch_bounds__(TPB, 4)
tucker_main_kernel(const float* __restrict__ x, float* __restrict__ out) {
    __shared__ float xs[RPB * XSTR];    // 34816 B; y aliased here after phase 1
    __shared__ float sfin[F_INq * Rq];  // 4096 B
    __shared__ float sH[Rq * F_OUTq];   // 4096 B

    const int bv   = blockIdx.y;
    const int t    = threadIdx.x;
    const int lane = t & 31;
    const int w    = t >> 5;
    const size_t base = ((size_t)bv * ROWS_PER_BV + (size_t)blockIdx.x * RPB) * (size_t)F_INq;

    // weights (both resident; no mid-kernel swap)
    #pragma unroll
    for (int i = 0; i < 8; ++i) {
        sfin[i * TPB + t] = g_finT[i * TPB + t];
        sH[i * TPB + t]   = g_H[bv * Rq * F_OUTq + i * TPB + t];
    }

    // stage x: 16 x (LDG.128 -> STS.128), stride-68 rows
    {
        const float4* gx = (const float4*)(x + base);
        #pragma unroll 4
        for (int it = 0; it < 16; ++it) {
            int i = it * TPB + t;
            float4 v = gx[i];
            *(float4*)&xs[(i >> 4) * XSTR + (i & 15) * 4] = v;
        }
    }
    __syncthreads();

    // ---- phase 1: y[row][r] = sum_a x[row][a] * finT[a][r]
    // warp roles: rh = w&1 -> r in [8*rh, 8*rh+8); rowh = w>>1 -> rows rowh*64 + lane + 32*i
    const int rh = w & 1, rowh = w >> 1;
    const int row0 = rowh * 64 + lane;
    unsigned long long acc[2][4];   // 2 rows x 8 r (f32x2)
    #pragma unroll
    for (int i = 0; i < 2; ++i)
        #pragma unroll
        for (int q = 0; q < 4; ++q) acc[i][q] = 0ull;

    {
        const int rb0 = row0 * XSTR, rb1 = (row0 + 32) * XSTR;
        #pragma unroll 4
        for (int ac = 0; ac < 16; ++ac) {            // 4 a per chunk
            // warp-uniform finT slice: 4 a x 8 r
            const ulonglong2* fp = (const ulonglong2*)&sfin[(4 * ac) * Rq + 8 * rh];
            ulonglong2 f0 = fp[0], f0b = fp[1];      // a0
            ulonglong2 f1 = ((const ulonglong2*)&sfin[(4 * ac + 1) * Rq + 8 * rh])[0];
            ulonglong2 f1b = ((const ulonglong2*)&sfin[(4 * ac + 1) * Rq + 8 * rh])[1];
            ulonglong2 f2 = ((const ulonglong2*)&sfin[(4 * ac + 2) * Rq + 8 * rh])[0];
            ulonglong2 f2b = ((const ulonglong2*)&sfin[(4 * ac + 2) * Rq + 8 * rh])[1];
            ulonglong2 f3 = ((const ulonglong2*)&sfin[(4 * ac + 3) * Rq + 8 * rh])[0];
            ulonglong2 f3b = ((const ulonglong2*)&sfin[(4 * ac + 3) * Rq + 8 * rh])[1];

            float4 xa0 = *(const float4*)&xs[rb0 + ac * 4];
            float4 xa1 = *(const float4*)&xs[rb1 + ac * 4];

            unsigned long long b;
            b = pack2(xa0.x);
            acc[0][0] = ffma2(b, f0.x,  acc[0][0]); acc[0][1] = ffma2(b, f0.y,  acc[0][1]);
            acc[0][2] = ffma2(b, f0b.x, acc[0][2]); acc[0][3] = ffma2(b, f0b.y, acc[0][3]);
            b = pack2(xa0.y);
            acc[0][0] = ffma2(b, f1.x,  acc[0][0]); acc[0][1] = ffma2(b, f1.y,  acc[0][1]);
            acc[0][2] = ffma2(b, f1b.x, acc[0][2]); acc[0][3] = ffma2(b, f1b.y, acc[0][3]);
            b = pack2(xa0.z);
            acc[0][0] = ffma2(b, f2.x,  acc[0][0]); acc[0][1] = ffma2(b, f2.y,  acc[0][1]);
            acc[0][2] = ffma2(b, f2b.x, acc[0][2]); acc[0][3] = ffma2(b, f2b.y, acc[0][3]);
            b = pack2(xa0.w);
            acc[0][0] = ffma2(b, f3.x,  acc[0][0]); acc[0][1] = ffma2(b, f3.y,  acc[0][1]);
            acc[0][2] = ffma2(b, f3b.x, acc[0][2]); acc[0][3] = ffma2(b, f3b.y, acc[0][3]);

            b = pack2(xa1.x);
            acc[1][0] = ffma2(b, f0.x,  acc[1][0]); acc[1][1] = ffma2(b, f0.y,  acc[1][1]);
            acc[1][2] = ffma2(b, f0b.x, acc[1][2]); acc[1][3] = ffma2(b, f0b.y, acc[1][3]);
            b = pack2(xa1.y);
            acc[1][0] = ffma2(b, f1.x,  acc[1][0]); acc[1][1] = ffma2(b, f1.y,  acc[1][1]);
            acc[1][2] = ffma2(b, f1b.x, acc[1][2]); acc[1][3] = ffma2(b, f1b.y, acc[1][3]);
            b = pack2(xa1.z);
            acc[1][0] = ffma2(b, f2.x,  acc[1][0]); acc[1][1] = ffma2(b, f2.y,  acc[1][1]);
            acc[1][2] = ffma2(b, f2b.x, acc[1][2]); acc[1][3] = ffma2(b, f2b.y, acc[1][3]);
            b = pack2(xa1.w);
            acc[1][0] = ffma2(b, f3.x,  acc[1][0]); acc[1][1] = ffma2(b, f3.y,  acc[1][1]);
            acc[1][2] = ffma2(b, f3b.x, acc[1][2]); acc[1][3] = ffma2(b, f3b.y, acc[1][3]);
        }
    }
    __syncthreads();   // all x reads done -> safe to overwrite xs with y

    // y-store: sy[row][r], stride 20, r-offset 8*rh; 4 x STS.128 conflict-free
    {
        float* sy = xs;
        #pragma unroll
        for (int i = 0; i < 2; ++i) {
            int row = row0 + 32 * i;
            *(ulonglong2*)&sy[row * YSTR + 8 * rh]     = make_ulonglong2(acc[i][0], acc[i][1]);
            *(ulonglong2*)&sy[row * YSTR + 8 * rh + 4] = make_ulonglong2(acc[i][2], acc[i][3]);
        }
    }
    __syncthreads();

    // ---- phase 2: out[row][e] = sum_r y[row][r] * H[r][e]
    // thread tile: 8 rows (rg + 16*i) x 8 e (eg*8..)
    {
        const float* sy = xs;
        const int eg = t >> 4, rg = t & 15;
        unsigned long long o2[8][4];
        #pragma unroll
        for (int i = 0; i < 8; ++i)
            #pragma unroll
            for (int q = 0; q < 4; ++q) o2[i][q] = 0ull;

        for (int rc = 0; rc < 4; ++rc) {             // r chunks of 4 (rolled: saves icache)
            ulonglong2 h[4][2];
            #pragma unroll
            for (int j = 0; j < 4; ++j) {
                const ulonglong2* hp = (const ulonglong2*)&sH[(4 * rc + j) * F_OUTq + eg * 8];
                h[j][0] = hp[0];
                h[j][1] = hp[1];
            }
            #pragma unroll
            for (int i = 0; i < 8; ++i) {
                float4 y4 = *(const float4*)&sy[(rg + 16 * i) * YSTR + rc * 4];
                unsigned long long b;
                b = pack2(y4.x);
                o2[i][0] = ffma2(b, h[0][0].x, o2[i][0]); o2[i][1] = ffma2(b, h[0][0].y, o2[i][1]);
                o2[i][2] = ffma2(b, h[0][1].x, o2[i][2]); o2[i][3] = ffma2(b, h[0][1].y, o2[i][3]);
                b = pack2(y4.y);
                o2[i][0] = ffma2(b, h[1][0].x, o2[i][0]); o2[i][1] = ffma2(b, h[1][0].y, o2[i][1]);
                o2[i][2] = ffma2(b, h[1][1].x, o2[i][2]); o2[i][3] = ffma2(b, h[1][1].y, o2[i][3]);
                b = pack2(y4.z);
                o2[i][0] = ffma2(b, h[2][0].x, o2[i][0]); o2[i][1] = ffma2(b, h[2][0].y, o2[i][1]);
                o2[i][2] = ffma2(b, h[2][1].x, o2[i][2]); o2[i][3] = ffma2(b, h[2][1].y, o2[i][3]);
                b = pack2(y4.w);
                o2[i][0] = ffma2(b, h[3][0].x, o2[i][0]); o2[i][1] = ffma2(b, h[3][0].y, o2[i][1]);
                o2[i][2] = ffma2(b, h[3][1].x, o2[i][2]); o2[i][3] = ffma2(b, h[3][1].y, o2[i][3]);
            }
        }

        // direct stores: 8 rows x 8 e, 2 x STG.128 per row
        float* ob = out + base;
        #pragma unroll
        for (int i = 0; i < 8; ++i) {
            float* p = ob + (size_t)(rg + 16 * i) * F_OUTq + eg * 8;
            *(ulonglong2*)(p)     = make_ulonglong2(o2[i][0], o2[i][1]);
            *(ulonglong2*)(p + 4) = make_ulonglong2(o2[i][2], o2[i][3]);
        }
    }
}

extern "C" void kernel_launch(void* const* d_in, const int* in_sizes, int n_in,
                              void* d_out, int out_size) {
    const float* x           = (const float*)d_in[0];
    const int*   var_idx     = (const int*)d_in[1];
    const float* core        = (const float*)d_in[2];
    const float* factor_vars = (const float*)d_in[3];
    const float* fac_in      = (const float*)d_in[4];
    const float* fac_out     = (const float*)d_in[5];
    float* out = (float*)d_out;

    precompute_kernel<<<BV, 64>>>(var_idx, core, factor_vars, fac_in, fac_out);

    dim3 grid(ROWS_PER_BV / RPB, BV);   // (512, 16)
    tucker_main_kernel<<<grid, TPB>>>(x, out);
}

// round 5
// speedup vs baseline: 1.3082x; 1.3082x over previous
#include <cuda_runtime.h>
#include <cuda_bf16.h>
#include <cstdint>

// ---- problem dims ----------------------------------------------------------
#define BV 16                      // B*V
#define ROWS_PER_BV 65536          // T*N*D
#define Mq 128                     // rows per block
#define Nq 64                      // F_OUT
#define Kq 64                      // F_IN
#define Rq 16
#define RVq 4
#define TPB 128

// ---- smem layout (dynamic) -------------------------------------------------
#define SM_AH  0                   // A hi: 128 rows x 128B (bf16) = 16384
#define SM_AL  16384               // A lo: 16384
#define SM_BFH 32768               // B frags hi: 4 kt x 8 nt x 32 lanes x uint2 = 8192
#define SM_BFL 40960               // B frags lo: 8192
#define SM_TOTAL 49152

#define SWZ(o) ((o) ^ (((o) >> 3) & 0x70))

// Precomputed B fragments in mma.m16n8k16 register layout:
// [bv][kt(4)][nt(8)][lane(32)] -> uint2 {b0, b1}
__device__ __align__(16) uint2 g_Bfh[BV * 4 * 8 * 32];
__device__ __align__(16) uint2 g_Bfl[BV * 4 * 8 * 32];

__device__ __forceinline__ uint32_t smem_u32(const void* p) {
    uint32_t a;
    asm("{ .reg .u64 t; cvta.to.shared.u64 t, %1; cvt.u32.u64 %0, t; }" : "=r"(a) : "l"(p));
    return a;
}

__device__ __forceinline__ uint32_t pack_bf16x2(float lo, float hi) {
    __nv_bfloat16 l = __float2bfloat16(lo), h = __float2bfloat16(hi);
    return ((uint32_t)__bfloat16_as_ushort(h) << 16) | __bfloat16_as_ushort(l);
}

__device__ __forceinline__ void ldmatrix_x4(uint32_t& r0, uint32_t& r1,
                                            uint32_t& r2, uint32_t& r3, uint32_t addr) {
    asm volatile("ldmatrix.sync.aligned.m8n8.x4.shared.b16 {%0,%1,%2,%3}, [%4];"
                 : "=r"(r0), "=r"(r1), "=r"(r2), "=r"(r3) : "r"(addr));
}

__device__ __forceinline__ void mma_bf16(float* c, const uint32_t* a, const uint2 b) {
    asm volatile(
        "mma.sync.aligned.m16n8k16.row.col.f32.bf16.bf16.f32 "
        "{%0,%1,%2,%3}, {%4,%5,%6,%7}, {%8,%9}, {%0,%1,%2,%3};"
        : "+f"(c[0]), "+f"(c[1]), "+f"(c[2]), "+f"(c[3])
        : "r"(a[0]), "r"(a[1]), "r"(a[2]), "r"(a[3]), "r"(b.x), "r"(b.y));
}

// ---- precompute: W[bv] -> bf16 hi/lo B-fragments ---------------------------
__global__ void precompute_kernel(const int* __restrict__ var_idx,
                                  const float* __restrict__ core,        // (RV, R, R)
                                  const float* __restrict__ factor_vars, // (NVAR, RV)
                                  const float* __restrict__ fac_in,      // (R, 64)
                                  const float* __restrict__ fac_out) {   // (R, 64)
    int bv = blockIdx.x;
    int e  = threadIdx.x;      // 0..63  (output column n = e)
    __shared__ float fvs[RVq];
    __shared__ float ceff[Rq * Rq];

    if (e < RVq) fvs[e] = factor_vars[var_idx[bv] * RVq + e];
    __syncthreads();
    for (int i = e; i < Rq * Rq; i += 64) {
        float s = 0.f;
        #pragma unroll
        for (int A = 0; A < RVq; ++A) s += fvs[A] * core[A * Rq * Rq + i];
        ceff[i] = s;
    }
    __syncthreads();

    float H[Rq];
    #pragma unroll
    for (int r = 0; r < Rq; ++r) {
        float s = 0.f;
        #pragma unroll
        for (int c = 0; c < Rq; ++c) s += ceff[r * Rq + c] * fac_out[c * Nq + e];
        H[r] = s;
    }
    // Wcol[a] = W[a][e] = sum_r fac_in[r][a] * H[r]
    float Wh[Kq], Wl[Kq];
    for (int a = 0; a < Kq; ++a) {
        float s = 0.f;
        #pragma unroll
        for (int r = 0; r < Rq; ++r) s += fac_in[r * Kq + a] * H[r];
        float hi = __bfloat162float(__float2bfloat16(s));
        Wh[a] = hi;
        Wl[a] = s - hi;
    }
    // fragment layout: col n=e -> nt=e>>3, owned by lanes (e&7)*4 + tig
    int nt = e >> 3, c4 = (e & 7) * 4;
    #pragma unroll
    for (int kt = 0; kt < 4; ++kt) {
        #pragma unroll
        for (int tig = 0; tig < 4; ++tig) {
            int lane = c4 + tig;
            int k0 = 16 * kt + 2 * tig;
            int idx = ((bv * 4 + kt) * 8 + nt) * 32 + lane;
            g_Bfh[idx] = make_uint2(pack_bf16x2(Wh[k0],     Wh[k0 + 1]),
                                    pack_bf16x2(Wh[k0 + 8], Wh[k0 + 9]));
            g_Bfl[idx] = make_uint2(pack_bf16x2(Wl[k0],     Wl[k0 + 1]),
                                    pack_bf16x2(Wl[k0 + 8], Wl[k0 + 9]));
        }
    }
}

// ---- main kernel -----------------------------------------------------------
extern __shared__ __align__(1024) char smem[];

__global__ void __launch_bounds__(TPB)
tucker_mma_kernel(const float* __restrict__ x, float* __restrict__ out) {
    const uint32_t sb = smem_u32(smem);
    const int bv = blockIdx.y;
    const int t  = threadIdx.x;
    const int w  = t >> 5, lane = t & 31;
    const size_t base = ((size_t)bv * ROWS_PER_BV + (size_t)blockIdx.x * Mq) * (size_t)Kq;

    // stage B fragments: 16 KB (hi+lo), vectorized
    {
        const uint4* gh = (const uint4*)(g_Bfh + bv * 1024);
        const uint4* gl = (const uint4*)(g_Bfl + bv * 1024);
        #pragma unroll
        for (int it = 0; it < 4; ++it) {
            int i = it * TPB + t;                        // 512 uint4 each
            *(uint4*)(smem + SM_BFH + i * 16) = gh[i];
            *(uint4*)(smem + SM_BFL + i * 16) = gl[i];
        }
    }

    // stage A: fp32 -> bf16 hi/lo, swizzled 128B rows
    {
        const float4* gx = (const float4*)(x + base);
        #pragma unroll
        for (int it = 0; it < 16; ++it) {
            int i = it * TPB + t;                        // float4 id: row=i>>4, col4=i&15
            float4 v = gx[i];
            float h0 = __bfloat162float(__float2bfloat16(v.x));
            float h1 = __bfloat162float(__float2bfloat16(v.y));
            float h2 = __bfloat162float(__float2bfloat16(v.z));
            float h3 = __bfloat162float(__float2bfloat16(v.w));
            uint32_t hiA = pack_bf16x2(h0, h1);
            uint32_t hiB = pack_bf16x2(h2, h3);
            uint32_t loA = pack_bf16x2(v.x - h0, v.y - h1);
            uint32_t loB = pack_bf16x2(v.z - h2, v.w - h3);
            uint32_t off = SWZ((uint32_t)((i >> 4) * 128 + (i & 15) * 8));
            *(uint2*)(smem + SM_AH + off) = make_uint2(hiA, hiB);
            *(uint2*)(smem + SM_AL + off) = make_uint2(loA, loB);
        }
    }
    __syncthreads();

    // accumulators: 2 m-tiles x 8 n-tiles x 4 floats
    float acc[2][8][4];
    #pragma unroll
    for (int mt = 0; mt < 2; ++mt)
        #pragma unroll
        for (int nt = 0; nt < 8; ++nt)
            #pragma unroll
            for (int q = 0; q < 4; ++q) acc[mt][nt][q] = 0.f;

    // ldmatrix address for this lane: row = m0 + (lane&15), kbyte = (kt*16 + (lane>>4)*8)*2
    const int arow = w * 32 + (lane & 15);
    const int koff = (lane >> 4) * 16;                   // bytes

    #pragma unroll
    for (int kt = 0; kt < 4; ++kt) {
        // B fragments for this k-tile (warp-lane indexed, conflict-free)
        uint2 bh[8], bl[8];
        #pragma unroll
        for (int nt = 0; nt < 8; ++nt) {
            uint32_t boff = ((kt * 8 + nt) * 32 + lane) * 8;
            bh[nt] = *(const uint2*)(smem + SM_BFH + boff);
            bl[nt] = *(const uint2*)(smem + SM_BFL + boff);
        }
        // A fragments: hi and lo, 2 m-tiles each
        uint32_t ah[2][4], al[2][4];
        #pragma unroll
        for (int mt = 0; mt < 2; ++mt) {
            uint32_t off = SWZ((uint32_t)((arow + mt * 16) * 128 + kt * 32 + koff));
            ldmatrix_x4(ah[mt][0], ah[mt][1], ah[mt][2], ah[mt][3], sb + SM_AH + off);
            ldmatrix_x4(al[mt][0], al[mt][1], al[mt][2], al[mt][3], sb + SM_AL + off);
        }
        // 3 error-compensated chains
        #pragma unroll
        for (int mt = 0; mt < 2; ++mt)
            #pragma unroll
            for (int nt = 0; nt < 8; ++nt) {
                mma_bf16(acc[mt][nt], ah[mt], bh[nt]);
                mma_bf16(acc[mt][nt], ah[mt], bl[nt]);
                mma_bf16(acc[mt][nt], al[mt], bh[nt]);
            }
    }

    // epilogue: direct stores. thread: rows w*32 + mt*16 + (lane>>2) (+8), cols nt*8+(lane&3)*2
    {
        float* ob = out + base;
        const int r0 = w * 32 + (lane >> 2);
        const int cc = (lane & 3) * 2;
        #pragma unroll
        for (int mt = 0; mt < 2; ++mt) {
            float* p0 = ob + (size_t)(r0 + mt * 16) * Nq + cc;
            float* p1 = p0 + 8 * Nq;
            #pragma unroll
            for (int nt = 0; nt < 8; ++nt) {
                *(float2*)(p0 + nt * 8) = make_float2(acc[mt][nt][0], acc[mt][nt][1]);
                *(float2*)(p1 + nt * 8) = make_float2(acc[mt][nt][2], acc[mt][nt][3]);
            }
        }
    }
}

extern "C" void kernel_launch(void* const* d_in, const int* in_sizes, int n_in,
                              void* d_out, int out_size) {
    const float* x           = (const float*)d_in[0];
    const int*   var_idx     = (const int*)d_in[1];
    const float* core        = (const float*)d_in[2];
    const float* factor_vars = (const float*)d_in[3];
    const float* fac_in      = (const float*)d_in[4];
    const float* fac_out     = (const float*)d_in[5];
    float* out = (float*)d_out;

    static bool attr_done = false;
    if (!attr_done) {
        cudaFuncSetAttribute(tucker_mma_kernel,
                             cudaFuncAttributeMaxDynamicSharedMemorySize, SM_TOTAL);
        attr_done = true;
    }

    precompute_kernel<<<BV, 64>>>(var_idx, core, factor_vars, fac_in, fac_out);

    dim3 grid(ROWS_PER_BV / Mq, BV);   // (512, 16)
    tucker_mma_kernel<<<grid, TPB, SM_TOTAL>>>(x, out);
}